// round 11
// baseline (speedup 1.0000x reference)
#include <cuda_runtime.h>
#include <cuda_fp16.h>
#include <cstdint>

// ---------------------------------------------------------------------------
// LinearAttention on GB300 (sm_103a via compute_103 PTX)
// Round 11: R8 GEMM config (best: 723us) + tensor-core attention core.
// Q/K/V GEMMs emit fp16 hi/lo pairs (fp32-exact to 2^-22); KV summarization
// and apply run as 3-term hi/lo mma kernels (ldmatrix.trans operands).
// B=4, S=4096, D=1024, H=16, hd=64
// ---------------------------------------------------------------------------

#define BATCH 4
#define SEQ   4096
#define EMB   1024
#define HEADS 16
#define HDIM  64
#define ROWS  (BATCH * SEQ)     // 16384
#define BH    (BATCH * HEADS)   // 64
#define KVSP  8                 // kv splits over S
#define KVSR  (SEQ / KVSP)      // 512

// GEMM tiling (R8 config — measured best)
#define MT 128
#define NTT 128
#define KC 32
#define KCH (EMB / KC)          // 32
#define STAGES 3
#define G_THREADS 256
#define PITCH16B 80             // 32 halfs + 16B pad
#define SZ_H16  (MT * PITCH16B)
#define OFF_AH  0
#define OFF_BH  (SZ_H16)
#define STAGE_BYTES (2 * SZ_H16)         // 20480
#define SMEM_DYN (STAGES * STAGE_BYTES)  // 61440 -> 2 CTAs/SM

// core tiles: 72-half pitch (144B; 16B-bank conflict-free, 16B-aligned rows)
#define CP 72

// ---------------------------------------------------------------------------
// Scratch
// ---------------------------------------------------------------------------
__device__ __align__(256) __half g_Xh[(size_t)ROWS * EMB];      // GEMM A operand
__device__ __align__(256) __half g_Wh[4][(size_t)EMB * EMB];    // weights [n][k]
__device__ __align__(256) __half g_Qh[(size_t)ROWS * EMB];
__device__ __align__(256) __half g_Ql[(size_t)ROWS * EMB];
__device__ __align__(256) __half g_Kh[(size_t)ROWS * EMB];
__device__ __align__(256) __half g_Kl[(size_t)ROWS * EMB];
__device__ __align__(256) __half g_Vh[(size_t)ROWS * EMB];
__device__ __align__(256) __half g_Vl[(size_t)ROWS * EMB];
__device__ float g_KVp[(size_t)KVSP * BH * HDIM * HDIM];
__device__ float g_Ksump[(size_t)KVSP * BH * HDIM];
__device__ __half g_KVh[(size_t)BH * HDIM * HDIM];
__device__ __half g_KVl[(size_t)BH * HDIM * HDIM];
__device__ float g_Ksum[(size_t)BH * HDIM];

// ---------------------------------------------------------------------------
// helpers
// ---------------------------------------------------------------------------
__device__ __forceinline__ uint32_t smem_u32(const void* p) {
    uint32_t a;
    asm("{ .reg .u64 t; cvta.to.shared.u64 t, %1; cvt.u32.u64 %0, t; }" : "=r"(a) : "l"(p));
    return a;
}
__device__ __forceinline__ void cp16(uint32_t saddr, const void* gaddr) {
    asm volatile("cp.async.cg.shared.global [%0], [%1], 16;" :: "r"(saddr), "l"(gaddr) : "memory");
}
__device__ __forceinline__ void ldsm4(uint32_t& r0, uint32_t& r1, uint32_t& r2,
                                      uint32_t& r3, uint32_t addr) {
    asm volatile("ldmatrix.sync.aligned.m8n8.x4.shared.b16 {%0,%1,%2,%3}, [%4];"
                 : "=r"(r0), "=r"(r1), "=r"(r2), "=r"(r3) : "r"(addr));
}
__device__ __forceinline__ void ldsm4t(uint32_t& r0, uint32_t& r1, uint32_t& r2,
                                       uint32_t& r3, uint32_t addr) {
    asm volatile("ldmatrix.sync.aligned.m8n8.x4.trans.shared.b16 {%0,%1,%2,%3}, [%4];"
                 : "=r"(r0), "=r"(r1), "=r"(r2), "=r"(r3) : "r"(addr));
}
__device__ __forceinline__ void mma_f16(float* c, const uint32_t* a, const uint32_t* b) {
    asm volatile(
        "mma.sync.aligned.m16n8k16.row.col.f32.f16.f16.f32 "
        "{%0,%1,%2,%3}, {%4,%5,%6,%7}, {%8,%9}, {%0,%1,%2,%3};"
        : "+f"(c[0]), "+f"(c[1]), "+f"(c[2]), "+f"(c[3])
        : "r"(a[0]), "r"(a[1]), "r"(a[2]), "r"(a[3]), "r"(b[0]), "r"(b[1]));
}
__device__ __forceinline__ __half2 split_hi(float v0, float v1, __half2& lo) {
    __half h0 = __float2half_rn(v0), h1 = __float2half_rn(v1);
    lo = __halves2half2(__float2half_rn(v0 - __half2float(h0)),
                        __float2half_rn(v1 - __half2float(h1)));
    return __halves2half2(h0, h1);
}

// ---------------------------------------------------------------------------
// GEMM: C = A @ Bt^T + bias (+elu+1). out_mode 0: fp32 C; 1: hi/lo fp16.
// Grid (8,128), 256 thr, warp tile 64x32, 3-stage cp.async, 2 CTAs/SM.
// ---------------------------------------------------------------------------
__global__ __launch_bounds__(G_THREADS, 2) void gemm_f16(
    const __half* __restrict__ A, const __half* __restrict__ B,
    const float* __restrict__ bias, float* __restrict__ C,
    __half* __restrict__ Chi, __half* __restrict__ Clo,
    int elu_mode, int out_mode)
{
    extern __shared__ char dsm[];
    const uint32_t dyn = smem_u32(dsm);
    const int tid  = threadIdx.x;
    const int wid  = tid >> 5;
    const int lane = tid & 31;
    const int m0 = blockIdx.y * MT;
    const int n0 = blockIdx.x * NTT;
    const int wm = (wid >> 2) * 64;
    const int wn = (wid & 3) * 32;

    auto load_stage = [&](int ch) {
        const uint32_t sb = dyn + (uint32_t)(ch % STAGES) * STAGE_BYTES;
        const int k0 = ch * KC;
        #pragma unroll
        for (int i = tid; i < 1024; i += G_THREADS) {
            const int half = i >> 9;
            const int rem  = i & 511;
            const int rr   = rem >> 2;
            const int g    = rem & 3;
            const __half* gp = half ? B : A;
            const int row = (half ? n0 : m0) + rr;
            cp16(sb + (uint32_t)half * SZ_H16 + (uint32_t)rr * PITCH16B + g * 16u,
                 gp + (size_t)row * EMB + k0 + g * 8);
        }
        asm volatile("cp.async.commit_group;" ::: "memory");
    };

    float acc[4][4][4];
    #pragma unroll
    for (int i = 0; i < 4; i++)
        #pragma unroll
        for (int j = 0; j < 4; j++)
            #pragma unroll
            for (int q = 0; q < 4; q++) acc[i][j][q] = 0.f;

    #pragma unroll
    for (int s = 0; s < STAGES - 1; s++) load_stage(s);

    for (int ch = 0; ch < KCH; ch++) {
        if (ch + STAGES - 1 < KCH) load_stage(ch + STAGES - 1);
        else asm volatile("cp.async.commit_group;" ::: "memory");
        asm volatile("cp.async.wait_group %0;" :: "n"(STAGES - 1) : "memory");
        __syncthreads();

        const uint32_t sb = dyn + (uint32_t)(ch % STAGES) * STAGE_BYTES;
        #pragma unroll
        for (int ks = 0; ks < 2; ks++) {
            const int kl = ks * 16;
            const int a_row = wm + (lane & 15);
            const int a_col = kl + (lane >> 4) * 8;
            const int b_row = wn + (lane & 7) + ((lane >> 4) & 1) * 8;
            const int b_col = kl + ((lane >> 3) & 1) * 8;

            uint32_t af[4][4];
            #pragma unroll
            for (int fm = 0; fm < 4; fm++) {
                uint32_t off = (uint32_t)(a_row + fm * 16) * PITCH16B + (uint32_t)a_col * 2u;
                ldsm4(af[fm][0], af[fm][1], af[fm][2], af[fm][3], sb + OFF_AH + off);
            }
            uint32_t bf[2][4];
            #pragma unroll
            for (int fp = 0; fp < 2; fp++) {
                uint32_t off = (uint32_t)(b_row + fp * 16) * PITCH16B + (uint32_t)b_col * 2u;
                ldsm4(bf[fp][0], bf[fp][1], bf[fp][2], bf[fp][3], sb + OFF_BH + off);
            }
            #pragma unroll
            for (int fm = 0; fm < 4; fm++)
                #pragma unroll
                for (int fn = 0; fn < 4; fn++)
                    mma_f16(acc[fm][fn], af[fm], &bf[fn >> 1][(fn & 1) * 2]);
        }
        __syncthreads();
    }

    const int er = lane >> 2;
    const int ec = (lane & 3) * 2;
    #pragma unroll
    for (int fn = 0; fn < 4; fn++) {
        const int col = n0 + wn + fn * 8 + ec;
        const float b0 = bias[col], b1 = bias[col + 1];
        #pragma unroll
        for (int fm = 0; fm < 4; fm++) {
            const int row = m0 + wm + fm * 16 + er;
            #pragma unroll
            for (int h = 0; h < 2; h++) {
                float v0 = acc[fm][fn][2 * h + 0] + b0;
                float v1 = acc[fm][fn][2 * h + 1] + b1;
                if (elu_mode) {
                    v0 = (v0 > 0.f) ? (v0 + 1.f) : __expf(v0);
                    v1 = (v1 > 0.f) ? (v1 + 1.f) : __expf(v1);
                }
                const size_t idx = (size_t)(row + 8 * h) * EMB + col;
                if (out_mode == 0) {
                    *(float2*)(C + idx) = make_float2(v0, v1);
                } else {
                    __half2 lo;
                    __half2 hi = split_hi(v0, v1, lo);
                    *(__half2*)(Chi + idx) = hi;
                    *(__half2*)(Clo + idx) = lo;
                }
            }
        }
    }
}

// ---------------------------------------------------------------------------
// fp32 -> fp16 (elementwise)
// ---------------------------------------------------------------------------
__global__ __launch_bounds__(256) void conv_f16(
    const float* __restrict__ X, __half* __restrict__ H)
{
    size_t i = ((size_t)blockIdx.x * 256 + threadIdx.x) * 4;
    float4 v = *(const float4*)(X + i);
    ushort4 hv;
    hv.x = __half_as_ushort(__float2half_rn(v.x));
    hv.y = __half_as_ushort(__float2half_rn(v.y));
    hv.z = __half_as_ushort(__float2half_rn(v.z));
    hv.w = __half_as_ushort(__float2half_rn(v.w));
    *(ushort4*)(H + i) = hv;
}

// ---------------------------------------------------------------------------
// Weight transpose + fp16: Wt[n][k] = W[k][n]
// ---------------------------------------------------------------------------
__global__ __launch_bounds__(256) void conv_w_t(
    const float* __restrict__ W, __half* __restrict__ H)
{
    __shared__ float tile[32][33];
    const int n0 = blockIdx.x * 32, k0 = blockIdx.y * 32;
    const int tx = threadIdx.x & 31, ty = threadIdx.x >> 5;
    #pragma unroll
    for (int j = 0; j < 32; j += 8)
        tile[ty + j][tx] = W[(size_t)(k0 + ty + j) * EMB + n0 + tx];
    __syncthreads();
    #pragma unroll
    for (int j = 0; j < 32; j += 8)
        H[(size_t)(n0 + ty + j) * EMB + k0 + tx] = __float2half_rn(tile[tx][ty + j]);
}

// ---------------------------------------------------------------------------
// Ksum partials: sum over s of (Kh+Kl). grid (BH, KVSP), 256 thr.
// ---------------------------------------------------------------------------
__global__ __launch_bounds__(256) void ksum_partial()
{
    const int bh = blockIdx.x, sp = blockIdx.y;
    const int b = bh >> 4, h = bh & 15;
    const int t = threadIdx.x;
    const int d = t & 63, q = t >> 6;          // q: 4 chunks of 128 s

    __shared__ float red[4][64];
    size_t base = ((size_t)(b * SEQ + sp * KVSR + q * 128)) * EMB + h * HDIM + d;
    float s = 0.f;
    #pragma unroll 8
    for (int i = 0; i < 128; i++) {
        size_t o = base + (size_t)i * EMB;
        s += __half2float(g_Kh[o]) + __half2float(g_Kl[o]);
    }
    red[q][d] = s;
    __syncthreads();
    if (t < 64)
        g_Ksump[((size_t)sp * BH + bh) * HDIM + t] =
            red[0][t] + red[1][t] + red[2][t] + red[3][t];
}

// ---------------------------------------------------------------------------
// KV partials via mma: KV[d][e] = sum_s K[s,d]*V[s,e] (3-term hi/lo).
// grid (BH, KVSP), 128 thr (4 warps, each n16 of e). Both operands .trans.
// ---------------------------------------------------------------------------
__global__ __launch_bounds__(128) void kv_partial_mma()
{
    __shared__ __half sT[2][4][16 * CP];   // stage, {Kh,Kl,Vh,Vl}, 16 rows x 72
    const int bh = blockIdx.x, sp = blockIdx.y;
    const int b = bh >> 4, h = bh & 15;
    const int tid = threadIdx.x;
    const int wid = tid >> 5;
    const int lane = tid & 31;
    const int e0 = wid * 16;
    const int s_begin = sp * KVSR;

    const __half* src[4];
    src[0] = g_Kh; src[1] = g_Kl; src[2] = g_Vh; src[3] = g_Vl;

    auto load_tile = [&](int it) {
        const int st = it & 1;
        const int s0 = s_begin + it * 16;
        #pragma unroll
        for (int i = tid; i < 512; i += 128) {
            const int arr = i >> 7, rem = i & 127;
            const int rr = rem >> 3, g = rem & 7;
            cp16(smem_u32(&sT[st][arr][rr * CP + g * 8]),
                 src[arr] + ((size_t)(b * SEQ + s0 + rr)) * EMB + h * HDIM + g * 8);
        }
        asm volatile("cp.async.commit_group;" ::: "memory");
    };

    float acc[4][2][4];
    #pragma unroll
    for (int i = 0; i < 4; i++)
        #pragma unroll
        for (int j = 0; j < 2; j++)
            #pragma unroll
            for (int q = 0; q < 4; q++) acc[i][j][q] = 0.f;

    // trans address patterns
    const int rA = (lane & 7) + ((lane >> 4) & 1) * 8;   // K row (s), matrices 0/1 s0-7, 2/3 s8-15
    const int cA8 = (lane >> 3) & 1;                     // d +8 for matrices 1/3
    const int rB = (lane & 7) + ((lane >> 3) & 1) * 8;   // V row (s), matrices 0/1 k0-15 @ e0
    const int cB8 = (lane >> 4) & 1;                     // e +8 for matrices 2/3

    load_tile(0);
    const int NIT = KVSR / 16;   // 32
    for (int it = 0; it < NIT; it++) {
        if (it + 1 < NIT) load_tile(it + 1);
        else asm volatile("cp.async.commit_group;" ::: "memory");
        asm volatile("cp.async.wait_group 1;" ::: "memory");
        __syncthreads();

        const int st = it & 1;
        const uint32_t kh = smem_u32(&sT[st][0][0]);
        const uint32_t kl = smem_u32(&sT[st][1][0]);
        const uint32_t vh = smem_u32(&sT[st][2][0]);
        const uint32_t vl = smem_u32(&sT[st][3][0]);

        uint32_t Ah[4][4], Al[4][4];
        #pragma unroll
        for (int fm = 0; fm < 4; fm++) {
            uint32_t off = (uint32_t)rA * (CP * 2) + (uint32_t)(fm * 16 + cA8 * 8) * 2u;
            ldsm4t(Ah[fm][0], Ah[fm][1], Ah[fm][2], Ah[fm][3], kh + off);
            ldsm4t(Al[fm][0], Al[fm][1], Al[fm][2], Al[fm][3], kl + off);
        }
        uint32_t Bh[4], Bl[4];
        {
            uint32_t off = (uint32_t)rB * (CP * 2) + (uint32_t)(e0 + cB8 * 8) * 2u;
            ldsm4t(Bh[0], Bh[1], Bh[2], Bh[3], vh + off);
            ldsm4t(Bl[0], Bl[1], Bl[2], Bl[3], vl + off);
        }
        #pragma unroll
        for (int fm = 0; fm < 4; fm++)
            #pragma unroll
            for (int fn = 0; fn < 2; fn++) {
                mma_f16(acc[fm][fn], Ah[fm], &Bh[fn * 2]);
                mma_f16(acc[fm][fn], Al[fm], &Bh[fn * 2]);
                mma_f16(acc[fm][fn], Ah[fm], &Bl[fn * 2]);
            }
        __syncthreads();
    }

    // write fp32 partials: KVp[sp*BH+bh][d*64+e]
    float* KVp = g_KVp + ((size_t)sp * BH + bh) * (HDIM * HDIM);
    const int er = lane >> 2, ec = (lane & 3) * 2;
    #pragma unroll
    for (int fm = 0; fm < 4; fm++)
        #pragma unroll
        for (int fn = 0; fn < 2; fn++) {
            const int col = e0 + fn * 8 + ec;
            #pragma unroll
            for (int hh = 0; hh < 2; hh++) {
                const int d = fm * 16 + er + 8 * hh;
                *(float2*)(KVp + (size_t)d * HDIM + col) =
                    make_float2(acc[fm][fn][2 * hh + 0], acc[fm][fn][2 * hh + 1]);
            }
        }
}

// ---------------------------------------------------------------------------
// Reduce partials; emit KV hi/lo fp16 + Ksum fp32.
// ---------------------------------------------------------------------------
__global__ __launch_bounds__(256) void kv_reduce()
{
    const int bh = blockIdx.x;
    const int t = threadIdx.x;
    for (int i = t; i < HDIM * HDIM; i += 256) {
        float s = 0.f;
        #pragma unroll
        for (int sp = 0; sp < KVSP; sp++)
            s += g_KVp[((size_t)sp * BH + bh) * (HDIM * HDIM) + i];
        __half hh = __float2half_rn(s);
        g_KVh[(size_t)bh * (HDIM * HDIM) + i] = hh;
        g_KVl[(size_t)bh * (HDIM * HDIM) + i] = __float2half_rn(s - __half2float(hh));
    }
    if (t < HDIM) {
        float s = 0.f;
        #pragma unroll
        for (int sp = 0; sp < KVSP; sp++)
            s += g_Ksump[((size_t)sp * BH + bh) * HDIM + t];
        g_Ksum[(size_t)bh * HDIM + t] = s;
    }
}

// ---------------------------------------------------------------------------
// Apply via mma: out[sq][e] = (Q·KV)[sq][e] / (Q·Ksum + 1e-6); fp16 out.
// grid (SEQ/64, BH), 128 thr (4 warps n16). A = Q non-trans, B = KV trans.
// ---------------------------------------------------------------------------
__global__ __launch_bounds__(128) void apply_mma()
{
    __shared__ __half sQh[64 * CP], sQl[64 * CP];
    __shared__ __half sKVh[64 * CP], sKVl[64 * CP];
    __shared__ float sKsum[HDIM], sInv[64];

    const int stile = blockIdx.x, bh = blockIdx.y;
    const int b = bh >> 4, h = bh & 15;
    const int tid = threadIdx.x;
    const int wid = tid >> 5;
    const int lane = tid & 31;
    const int e0 = wid * 16;
    const int sq0 = stile * 64;

    // stage tiles: Qh/Ql rows sq (64x64), KVh/KVl rows d (64x64)
    #pragma unroll
    for (int i = tid; i < 512; i += 128) {
        const int rr = i >> 3, g = i & 7;
        const size_t qoff = ((size_t)(b * SEQ + sq0 + rr)) * EMB + h * HDIM + g * 8;
        cp16(smem_u32(&sQh[rr * CP + g * 8]), g_Qh + qoff);
        cp16(smem_u32(&sQl[rr * CP + g * 8]), g_Ql + qoff);
        const size_t koff = (size_t)bh * (HDIM * HDIM) + (size_t)rr * HDIM + g * 8;
        cp16(smem_u32(&sKVh[rr * CP + g * 8]), g_KVh + koff);
        cp16(smem_u32(&sKVl[rr * CP + g * 8]), g_KVl + koff);
    }
    asm volatile("cp.async.commit_group;" ::: "memory");
    if (tid < HDIM) sKsum[tid] = g_Ksum[(size_t)bh * HDIM + tid];
    asm volatile("cp.async.wait_group 0;" ::: "memory");
    __syncthreads();

    // norm per row (threads 0..63): dot(Qh+Ql, Ksum), vectorized row reads
    if (tid < 64) {
        float nrm = 0.f;
        #pragma unroll
        for (int g = 0; g < 8; g++) {
            uint4 uh = *(uint4*)&sQh[tid * CP + g * 8];
            uint4 ul = *(uint4*)&sQl[tid * CP + g * 8];
            const uint32_t* hp = (const uint32_t*)&uh;
            const uint32_t* lp = (const uint32_t*)&ul;
            #pragma unroll
            for (int p = 0; p < 4; p++) {
                float2 fh = __half22float2(*(const __half2*)&hp[p]);
                float2 fl = __half22float2(*(const __half2*)&lp[p]);
                nrm += (fh.x + fl.x) * sKsum[g * 8 + 2 * p]
                     + (fh.y + fl.y) * sKsum[g * 8 + 2 * p + 1];
            }
        }
        sInv[tid] = 1.f / (nrm + 1e-6f);
    }
    __syncthreads();

    float acc[4][2][4];
    #pragma unroll
    for (int i = 0; i < 4; i++)
        #pragma unroll
        for (int j = 0; j < 2; j++)
            #pragma unroll
            for (int q = 0; q < 4; q++) acc[i][j][q] = 0.f;

    const uint32_t qh = smem_u32(sQh), ql = smem_u32(sQl);
    const uint32_t kvh = smem_u32(sKVh), kvl = smem_u32(sKVl);
    const int a_row = lane & 15;
    const int a_c8  = lane >> 4;                 // +8 halfs for k upper
    const int rB = (lane & 7) + ((lane >> 3) & 1) * 8;
    const int cB8 = (lane >> 4) & 1;

    #pragma unroll
    for (int kk = 0; kk < 4; kk++) {             // k = d, 4 steps of 16
        uint32_t Ahf[4][4], Alf[4][4];
        #pragma unroll
        for (int fm = 0; fm < 4; fm++) {
            uint32_t off = (uint32_t)(a_row + fm * 16) * (CP * 2)
                         + (uint32_t)(kk * 16 + a_c8 * 8) * 2u;
            ldsm4(Ahf[fm][0], Ahf[fm][1], Ahf[fm][2], Ahf[fm][3], qh + off);
            ldsm4(Alf[fm][0], Alf[fm][1], Alf[fm][2], Alf[fm][3], ql + off);
        }
        uint32_t Bh[4], Bl[4];
        {
            uint32_t off = (uint32_t)(rB + kk * 16) * (CP * 2)
                         + (uint32_t)(e0 + cB8 * 8) * 2u;
            ldsm4t(Bh[0], Bh[1], Bh[2], Bh[3], kvh + off);
            ldsm4t(Bl[0], Bl[1], Bl[2], Bl[3], kvl + off);
        }
        #pragma unroll
        for (int fm = 0; fm < 4; fm++)
            #pragma unroll
            for (int fn = 0; fn < 2; fn++) {
                mma_f16(acc[fm][fn], Ahf[fm], &Bh[fn * 2]);
                mma_f16(acc[fm][fn], Alf[fm], &Bh[fn * 2]);
                mma_f16(acc[fm][fn], Ahf[fm], &Bl[fn * 2]);
            }
    }

    // epilogue: normalize, write fp16 into g_Xh
    const int er = lane >> 2, ec = (lane & 3) * 2;
    #pragma unroll
    for (int fm = 0; fm < 4; fm++)
        #pragma unroll
        for (int fn = 0; fn < 2; fn++) {
            const int col = e0 + fn * 8 + ec;
            #pragma unroll
            for (int hh = 0; hh < 2; hh++) {
                const int m = fm * 16 + er + 8 * hh;
                const float inv = sInv[m];
                __half2 o = __halves2half2(
                    __float2half_rn(acc[fm][fn][2 * hh + 0] * inv),
                    __float2half_rn(acc[fm][fn][2 * hh + 1] * inv));
                *(__half2*)(g_Xh + ((size_t)(b * SEQ + sq0 + m)) * EMB
                            + h * HDIM + col) = o;
            }
        }
}

// ---------------------------------------------------------------------------
// Launch
// ---------------------------------------------------------------------------
extern "C" void kernel_launch(void* const* d_in, const int* in_sizes, int n_in,
                              void* d_out, int out_size)
{
    const float* query = (const float*)d_in[0];
    const float* keyv  = (const float*)d_in[1];
    const float* W[4] = { (const float*)d_in[2], (const float*)d_in[4],
                          (const float*)d_in[6], (const float*)d_in[8] };
    const float* bq = (const float*)d_in[3];
    const float* bk = (const float*)d_in[5];
    const float* bv = (const float*)d_in[7];
    const float* bo = (const float*)d_in[9];
    float* out = (float*)d_out;

    __half *pXh, *pQh, *pQl, *pKh, *pKl, *pVh, *pVl;
    __half (*pWh)[(size_t)EMB * EMB];
    cudaGetSymbolAddress((void**)&pXh, g_Xh);
    cudaGetSymbolAddress((void**)&pQh, g_Qh);
    cudaGetSymbolAddress((void**)&pQl, g_Ql);
    cudaGetSymbolAddress((void**)&pKh, g_Kh);
    cudaGetSymbolAddress((void**)&pKl, g_Kl);
    cudaGetSymbolAddress((void**)&pVh, g_Vh);
    cudaGetSymbolAddress((void**)&pVl, g_Vl);
    cudaGetSymbolAddress((void**)&pWh, g_Wh);

    static bool attr_set = false;
    if (!attr_set) {
        cudaFuncSetAttribute(gemm_f16, cudaFuncAttributeMaxDynamicSharedMemorySize, SMEM_DYN);
        attr_set = true;
    }

    const dim3 wgrid(EMB / 32, EMB / 32);
    const dim3 ggrid(EMB / NTT, ROWS / MT);
    const int conv_blocks = (int)(((size_t)ROWS * EMB / 4) / 256);

    for (int w = 0; w < 4; w++)
        conv_w_t<<<wgrid, 256>>>(W[w], pWh[w]);

    // Q projection -> hi/lo (elu fused)
    conv_f16<<<conv_blocks, 256>>>(query, pXh);
    gemm_f16<<<ggrid, G_THREADS, SMEM_DYN>>>(pXh, pWh[0], bq, nullptr, pQh, pQl, 1, 1);

    // K/V projections -> hi/lo
    conv_f16<<<conv_blocks, 256>>>(keyv, pXh);
    gemm_f16<<<ggrid, G_THREADS, SMEM_DYN>>>(pXh, pWh[1], bk, nullptr, pKh, pKl, 1, 1);
    gemm_f16<<<ggrid, G_THREADS, SMEM_DYN>>>(pXh, pWh[2], bv, nullptr, pVh, pVl, 0, 1);

    // attention core (tensor-pipe)
    ksum_partial<<<dim3(BH, KVSP), 256>>>();
    kv_partial_mma<<<dim3(BH, KVSP), 128>>>();
    kv_reduce<<<BH, 256>>>();
    apply_mma<<<dim3(SEQ / 64, BH), 128>>>();    // writes fp16 into g_Xh

    // output projection (fp32 out)
    gemm_f16<<<ggrid, G_THREADS, SMEM_DYN>>>(pXh, pWh[3], bo, out, nullptr, nullptr, 0, 0);
}

// round 13
// speedup vs baseline: 1.3809x; 1.3809x over previous
#include <cuda_runtime.h>
#include <cuda_fp16.h>
#include <cstdint>

// ---------------------------------------------------------------------------
// LinearAttention on GB300 (sm_103a via compute_103 PTX)
// Round 12: R8 numerics exactly (canary rel_err 4.3296e-4) + structural fuse:
//   - Q/K/V projections in ONE GEMM launch (3072 CTAs: 11 waves vs 12)
//   - 4 weight transposes in one launch; both activation converts in one
// B=4, S=4096, D=1024, H=16, hd=64
// ---------------------------------------------------------------------------

#define BATCH 4
#define SEQ   4096
#define EMB   1024
#define HEADS 16
#define HDIM  64
#define ROWS  (BATCH * SEQ)     // 16384
#define BH    (BATCH * HEADS)   // 64
#define SPLITS 16
#define SROWS (SEQ / SPLITS)    // 256

// GEMM tiling (R8 config — measured best)
#define MT 128
#define NTT 128
#define KC 32
#define KCH (EMB / KC)          // 32
#define STAGES 3
#define G_THREADS 256
#define PITCH16B 80             // 32 halfs + 16B pad (ldmatrix conflict-free)
#define SZ_H16  (MT * PITCH16B)          // 10240
#define OFF_AH  0
#define OFF_BH  (SZ_H16)
#define STAGE_BYTES (2 * SZ_H16)         // 20480
#define SMEM_DYN (STAGES * STAGE_BYTES)  // 61440 -> 2 CTAs/SM

// ---------------------------------------------------------------------------
// Scratch
// ---------------------------------------------------------------------------
__device__ __align__(256) float g_Q[(size_t)ROWS * EMB];
__device__ __align__(256) float g_K[(size_t)ROWS * EMB];
__device__ __align__(256) float g_V[(size_t)ROWS * EMB];
__device__ __align__(256) __half g_Xq[(size_t)ROWS * EMB];      // query fp16
__device__ __align__(256) __half g_Xh[(size_t)ROWS * EMB];      // keyv fp16 / attn out
__device__ __align__(256) __half g_Wh[4][(size_t)EMB * EMB];    // weights [n][k]
__device__ float g_KVp[(size_t)SPLITS * BH * HDIM * HDIM];
__device__ float g_Ksump[(size_t)SPLITS * BH * HDIM];
__device__ float g_KV[(size_t)BH * HDIM * HDIM];
__device__ float g_Ksum[(size_t)BH * HDIM];

// ---------------------------------------------------------------------------
// helpers
// ---------------------------------------------------------------------------
__device__ __forceinline__ uint32_t smem_u32(const void* p) {
    uint32_t a;
    asm("{ .reg .u64 t; cvta.to.shared.u64 t, %1; cvt.u32.u64 %0, t; }" : "=r"(a) : "l"(p));
    return a;
}
__device__ __forceinline__ void cp16(uint32_t saddr, const void* gaddr) {
    asm volatile("cp.async.cg.shared.global [%0], [%1], 16;" :: "r"(saddr), "l"(gaddr) : "memory");
}
__device__ __forceinline__ void ldsm4(uint32_t& r0, uint32_t& r1, uint32_t& r2,
                                      uint32_t& r3, uint32_t addr) {
    asm volatile("ldmatrix.sync.aligned.m8n8.x4.shared.b16 {%0,%1,%2,%3}, [%4];"
                 : "=r"(r0), "=r"(r1), "=r"(r2), "=r"(r3) : "r"(addr));
}
__device__ __forceinline__ void mma_f16(float* c, const uint32_t* a, const uint32_t* b) {
    asm volatile(
        "mma.sync.aligned.m16n8k16.row.col.f32.f16.f16.f32 "
        "{%0,%1,%2,%3}, {%4,%5,%6,%7}, {%8,%9}, {%0,%1,%2,%3};"
        : "+f"(c[0]), "+f"(c[1]), "+f"(c[2]), "+f"(c[3])
        : "r"(a[0]), "r"(a[1]), "r"(a[2]), "r"(a[3]), "r"(b[0]), "r"(b[1]));
}

// ---------------------------------------------------------------------------
// GEMM: per-CTA sub-GEMM select. nsub=3: blockIdx.x in [0,24), sub=x>>3
// (0:Q uses A0, 1:K uses A1, 2:V uses A1); nsub=1: x in [0,8), sub=0.
// B = Wbase + sub*EMB*EMB. elu for sub<2 when nsub==3 (Q,K), else none.
// ---------------------------------------------------------------------------
__global__ __launch_bounds__(G_THREADS, 2) void gemm_f16(
    const __half* __restrict__ A0, const __half* __restrict__ A1,
    const __half* __restrict__ Wbase,
    const float* __restrict__ b0, const float* __restrict__ b1,
    const float* __restrict__ b2,
    float* __restrict__ C0, float* __restrict__ C1, float* __restrict__ C2,
    int nsub)
{
    extern __shared__ char dsm[];
    const uint32_t dyn = smem_u32(dsm);

    const int tid  = threadIdx.x;
    const int wid  = tid >> 5;
    const int lane = tid & 31;
    const int sub  = (nsub == 3) ? (blockIdx.x >> 3) : 0;
    const int m0 = blockIdx.y * MT;
    const int n0 = (blockIdx.x & 7) * NTT;
    const int wm = (wid >> 2) * 64;
    const int wn = (wid & 3) * 32;

    const __half* A = (sub == 0) ? A0 : A1;
    const __half* B = Wbase + (size_t)sub * EMB * EMB;
    const float* bias = (sub == 0) ? b0 : (sub == 1) ? b1 : b2;
    float* C = (sub == 0) ? C0 : (sub == 1) ? C1 : C2;
    const int elu_mode = (nsub == 3) ? (sub < 2) : 0;

    auto load_stage = [&](int ch) {
        const uint32_t sb = dyn + (uint32_t)(ch % STAGES) * STAGE_BYTES;
        const int k0 = ch * KC;
        #pragma unroll
        for (int i = tid; i < 1024; i += G_THREADS) {
            const int half = i >> 9;
            const int rem  = i & 511;
            const int rr   = rem >> 2;
            const int g    = rem & 3;
            const __half* gp = half ? B : A;
            const int row = (half ? n0 : m0) + rr;
            cp16(sb + (uint32_t)half * SZ_H16 + (uint32_t)rr * PITCH16B + g * 16u,
                 gp + (size_t)row * EMB + k0 + g * 8);
        }
        asm volatile("cp.async.commit_group;" ::: "memory");
    };

    float acc[4][4][4];
    #pragma unroll
    for (int i = 0; i < 4; i++)
        #pragma unroll
        for (int j = 0; j < 4; j++)
            #pragma unroll
            for (int q = 0; q < 4; q++) acc[i][j][q] = 0.f;

    #pragma unroll
    for (int s = 0; s < STAGES - 1; s++) load_stage(s);

    for (int ch = 0; ch < KCH; ch++) {
        if (ch + STAGES - 1 < KCH) load_stage(ch + STAGES - 1);
        else asm volatile("cp.async.commit_group;" ::: "memory");
        asm volatile("cp.async.wait_group %0;" :: "n"(STAGES - 1) : "memory");
        __syncthreads();

        const uint32_t sb = dyn + (uint32_t)(ch % STAGES) * STAGE_BYTES;
        #pragma unroll
        for (int ks = 0; ks < 2; ks++) {
            const int kl = ks * 16;
            const int a_row = wm + (lane & 15);
            const int a_col = kl + (lane >> 4) * 8;
            const int b_row = wn + (lane & 7) + ((lane >> 4) & 1) * 8;
            const int b_col = kl + ((lane >> 3) & 1) * 8;

            uint32_t af[4][4];
            #pragma unroll
            for (int fm = 0; fm < 4; fm++) {
                uint32_t off = (uint32_t)(a_row + fm * 16) * PITCH16B + (uint32_t)a_col * 2u;
                ldsm4(af[fm][0], af[fm][1], af[fm][2], af[fm][3], sb + OFF_AH + off);
            }
            uint32_t bf[2][4];
            #pragma unroll
            for (int fp = 0; fp < 2; fp++) {
                uint32_t off = (uint32_t)(b_row + fp * 16) * PITCH16B + (uint32_t)b_col * 2u;
                ldsm4(bf[fp][0], bf[fp][1], bf[fp][2], bf[fp][3], sb + OFF_BH + off);
            }
            #pragma unroll
            for (int fm = 0; fm < 4; fm++)
                #pragma unroll
                for (int fn = 0; fn < 4; fn++)
                    mma_f16(acc[fm][fn], af[fm], &bf[fn >> 1][(fn & 1) * 2]);
        }
        __syncthreads();
    }

    const int er = lane >> 2;
    const int ec = (lane & 3) * 2;
    #pragma unroll
    for (int fn = 0; fn < 4; fn++) {
        const int col = n0 + wn + fn * 8 + ec;
        const float bb0 = bias[col], bb1 = bias[col + 1];
        #pragma unroll
        for (int fm = 0; fm < 4; fm++) {
            const int row = m0 + wm + fm * 16 + er;
            #pragma unroll
            for (int h = 0; h < 2; h++) {
                float v0 = acc[fm][fn][2 * h + 0] + bb0;
                float v1 = acc[fm][fn][2 * h + 1] + bb1;
                if (elu_mode) {
                    v0 = (v0 > 0.f) ? (v0 + 1.f) : __expf(v0);
                    v1 = (v1 > 0.f) ? (v1 + 1.f) : __expf(v1);
                }
                *(float2*)(C + (size_t)(row + 8 * h) * EMB + col) = make_float2(v0, v1);
            }
        }
    }
}

// ---------------------------------------------------------------------------
// fp32 -> fp16, two tensors in one launch (grid.y selects)
// ---------------------------------------------------------------------------
__global__ __launch_bounds__(256) void conv2_f16(
    const float* __restrict__ X0, const float* __restrict__ X1,
    __half* __restrict__ H0, __half* __restrict__ H1)
{
    const float* X = blockIdx.y ? X1 : X0;
    __half* H = blockIdx.y ? H1 : H0;
    size_t i = ((size_t)blockIdx.x * 256 + threadIdx.x) * 4;
    float4 v = *(const float4*)(X + i);
    ushort4 hv;
    hv.x = __half_as_ushort(__float2half_rn(v.x));
    hv.y = __half_as_ushort(__float2half_rn(v.y));
    hv.z = __half_as_ushort(__float2half_rn(v.z));
    hv.w = __half_as_ushort(__float2half_rn(v.w));
    *(ushort4*)(H + i) = hv;
}

// ---------------------------------------------------------------------------
// Weight transpose + fp16, all 4 weights in one launch (grid.z selects)
// ---------------------------------------------------------------------------
__global__ __launch_bounds__(256) void conv_w_all(
    const float* __restrict__ W0, const float* __restrict__ W1,
    const float* __restrict__ W2, const float* __restrict__ W3,
    __half* __restrict__ Hbase)
{
    __shared__ float tile[32][33];
    const int z = blockIdx.z;
    const float* W = (z == 0) ? W0 : (z == 1) ? W1 : (z == 2) ? W2 : W3;
    __half* H = Hbase + (size_t)z * EMB * EMB;
    const int n0 = blockIdx.x * 32, k0 = blockIdx.y * 32;
    const int tx = threadIdx.x & 31, ty = threadIdx.x >> 5;
    #pragma unroll
    for (int j = 0; j < 32; j += 8)
        tile[ty + j][tx] = W[(size_t)(k0 + ty + j) * EMB + n0 + tx];
    __syncthreads();
    #pragma unroll
    for (int j = 0; j < 32; j += 8)
        H[(size_t)(n0 + ty + j) * EMB + k0 + tx] = __float2half_rn(tile[tx][ty + j]);
}

// ---------------------------------------------------------------------------
// KV summarization (R8 config): 4x4 register tile, float4 LDS; fused ksum.
// ---------------------------------------------------------------------------
#define KVCH 16

__global__ __launch_bounds__(256) void kv_partial()
{
    const int bh = blockIdx.x, sp = blockIdx.y;
    const int b = bh / HEADS, h = bh % HEADS;
    const int t = threadIdx.x;
    const int d0 = (t & 15) * 4;
    const int e0 = (t >> 4) * 4;

    __shared__ float Ks[KVCH][HDIM];
    __shared__ float Vs[KVCH][HDIM];

    float acc[4][4];
    #pragma unroll
    for (int i = 0; i < 4; i++)
        #pragma unroll
        for (int j = 0; j < 4; j++) acc[i][j] = 0.f;
    float ksum[4] = {0.f, 0.f, 0.f, 0.f};

    const float* Kbase = g_K + (size_t)b * SEQ * EMB + h * HDIM;
    const float* Vbase = g_V + (size_t)b * SEQ * EMB + h * HDIM;

    const int lr = t >> 4, lc = (t & 15) * 4;
    const int s_begin = sp * SROWS;
    for (int s0 = s_begin; s0 < s_begin + SROWS; s0 += KVCH) {
        *(float4*)&Ks[lr][lc] = *(const float4*)(Kbase + (size_t)(s0 + lr) * EMB + lc);
        *(float4*)&Vs[lr][lc] = *(const float4*)(Vbase + (size_t)(s0 + lr) * EMB + lc);
        __syncthreads();
        #pragma unroll
        for (int ss = 0; ss < KVCH; ss++) {
            float4 kk = *(const float4*)&Ks[ss][d0];
            float4 vv = *(const float4*)&Vs[ss][e0];
            const float* kp = (const float*)&kk;
            const float* vp = (const float*)&vv;
            #pragma unroll
            for (int i = 0; i < 4; i++) {
                ksum[i] += kp[i];
                #pragma unroll
                for (int j = 0; j < 4; j++)
                    acc[i][j] += kp[i] * vp[j];
            }
        }
        __syncthreads();
    }

    float* KVp = g_KVp + ((size_t)sp * BH + bh) * HDIM * HDIM;
    #pragma unroll
    for (int i = 0; i < 4; i++)
        *(float4*)(KVp + (size_t)(d0 + i) * HDIM + e0) = *(float4*)acc[i];
    if (t < 16) {
        #pragma unroll
        for (int i = 0; i < 4; i++)
            g_Ksump[((size_t)sp * BH + bh) * HDIM + d0 + i] = ksum[i];
    }
}

__global__ __launch_bounds__(256) void kv_reduce()
{
    const int bh = blockIdx.x;
    const int t = threadIdx.x;
    for (int i = t; i < HDIM * HDIM; i += 256) {
        float s = 0.f;
        #pragma unroll
        for (int sp = 0; sp < SPLITS; sp++)
            s += g_KVp[((size_t)sp * BH + bh) * HDIM * HDIM + i];
        g_KV[(size_t)bh * HDIM * HDIM + i] = s;
    }
    if (t < HDIM) {
        float s = 0.f;
        #pragma unroll
        for (int sp = 0; sp < SPLITS; sp++)
            s += g_Ksump[((size_t)sp * BH + bh) * HDIM + t];
        g_Ksum[(size_t)bh * HDIM + t] = s;
    }
}

// ---------------------------------------------------------------------------
// Apply: attn = (Q·KV)/(Q·Ksum+1e-6); writes fp16 operand into g_Xh.
// ---------------------------------------------------------------------------
__global__ __launch_bounds__(256) void apply_attn()
{
    const int stile = blockIdx.x;
    const int bh = blockIdx.y;
    const int b = bh / HEADS, h = bh % HEADS;
    const int t = threadIdx.x;

    __shared__ float Qt[HDIM][64];
    __shared__ float KVs[HDIM][HDIM];
    __shared__ float Ksums[HDIM];

    const int s0 = stile * 64;
    const float* Qbase = g_Q + (size_t)(b * SEQ + s0) * EMB + h * HDIM;

    #pragma unroll
    for (int k = 0; k < 16; k++) {
        int idx = t + 256 * k;
        int rr = idx >> 6, cc = idx & 63;
        Qt[cc][rr] = Qbase[(size_t)rr * EMB + cc];
        KVs[rr][cc] = g_KV[(size_t)bh * HDIM * HDIM + idx];
    }
    if (t < HDIM) Ksums[t] = g_Ksum[(size_t)bh * HDIM + t];
    __syncthreads();

    const int r0 = (t & 15) * 4;
    const int e0 = (t >> 4) * 4;

    float acc[4][4];
    #pragma unroll
    for (int i = 0; i < 4; i++)
        #pragma unroll
        for (int j = 0; j < 4; j++) acc[i][j] = 0.f;
    float nrm[4] = {0.f, 0.f, 0.f, 0.f};

    #pragma unroll
    for (int dd = 0; dd < HDIM; dd++) {
        float4 qq = *(const float4*)&Qt[dd][r0];
        float4 vv = *(const float4*)&KVs[dd][e0];
        const float* qp = (const float*)&qq;
        const float* vp = (const float*)&vv;
        float ks = Ksums[dd];
        #pragma unroll
        for (int i = 0; i < 4; i++) {
            nrm[i] += qp[i] * ks;
            #pragma unroll
            for (int j = 0; j < 4; j++)
                acc[i][j] += qp[i] * vp[j];
        }
    }

    #pragma unroll
    for (int i = 0; i < 4; i++) {
        float inv = 1.f / (nrm[i] + 1e-6f);
        size_t obase = (size_t)(b * SEQ + s0 + r0 + i) * EMB + h * HDIM + e0;
        ushort4 hv;
        hv.x = __half_as_ushort(__float2half_rn(acc[i][0] * inv));
        hv.y = __half_as_ushort(__float2half_rn(acc[i][1] * inv));
        hv.z = __half_as_ushort(__float2half_rn(acc[i][2] * inv));
        hv.w = __half_as_ushort(__float2half_rn(acc[i][3] * inv));
        *(ushort4*)(g_Xh + obase) = hv;
    }
}

// ---------------------------------------------------------------------------
// Launch
// ---------------------------------------------------------------------------
extern "C" void kernel_launch(void* const* d_in, const int* in_sizes, int n_in,
                              void* d_out, int out_size)
{
    const float* query = (const float*)d_in[0];
    const float* keyv  = (const float*)d_in[1];
    const float* Wq = (const float*)d_in[2];
    const float* bq = (const float*)d_in[3];
    const float* Wk = (const float*)d_in[4];
    const float* bk = (const float*)d_in[5];
    const float* Wv = (const float*)d_in[6];
    const float* bv = (const float*)d_in[7];
    const float* Wo = (const float*)d_in[8];
    const float* bo = (const float*)d_in[9];
    float* out = (float*)d_out;

    float *pQ, *pK, *pV;
    __half *pXq, *pXh;
    __half (*pWh)[(size_t)EMB * EMB];
    cudaGetSymbolAddress((void**)&pQ, g_Q);
    cudaGetSymbolAddress((void**)&pK, g_K);
    cudaGetSymbolAddress((void**)&pV, g_V);
    cudaGetSymbolAddress((void**)&pXq, g_Xq);
    cudaGetSymbolAddress((void**)&pXh, g_Xh);
    cudaGetSymbolAddress((void**)&pWh, g_Wh);

    static bool attr_set = false;
    if (!attr_set) {
        cudaFuncSetAttribute(gemm_f16, cudaFuncAttributeMaxDynamicSharedMemorySize, SMEM_DYN);
        attr_set = true;
    }

    const int conv_blocks = (int)(((size_t)ROWS * EMB / 4) / 256);  // 16384

    // All weight transposes in one launch; both activation converts in one.
    conv_w_all<<<dim3(EMB / 32, EMB / 32, 4), 256>>>(Wq, Wk, Wv, Wo, pWh[0]);
    conv2_f16<<<dim3(conv_blocks, 2), 256>>>(query, keyv, pXq, pXh);

    // Q/K/V projections fused: 3072 CTAs (11 waves vs 12).
    gemm_f16<<<dim3(24, ROWS / MT), G_THREADS, SMEM_DYN>>>(
        pXq, pXh, pWh[0], bq, bk, bv, pQ, pK, pV, 3);

    // Linear-attention core (fp32, R8 config)
    kv_partial<<<dim3(BH, SPLITS), 256>>>();
    kv_reduce<<<BH, 256>>>();
    apply_attn<<<dim3(SEQ / 64, BH), 256>>>();   // writes fp16 into g_Xh

    // Output projection
    gemm_f16<<<dim3(8, ROWS / MT), G_THREADS, SMEM_DYN>>>(
        pXh, pXh, pWh[3], bo, bo, bo, out, out, out, 1);
}